// round 5
// baseline (speedup 1.0000x reference)
#include <cuda_runtime.h>
#include <math_constants.h>
#include <math.h>

#define BSZ 4
#define NP  2048
#define EPSF 1e-6f
#define INF  CUDART_INF_F

// ---------------- scratch ----------------
__device__ float g_knn[2][BSZ][NP * 3];   // sqrt'd 3NN (incl self): real=0, fake=1
__device__ float g_sel[14][14];           // selected order statistics
__device__ float g_hex_partial[256];
__device__ float g_feas_partial[128];

// ---------------- packed f32x2 helpers ----------------
__device__ __forceinline__ unsigned long long pk(float a, float b) {
    unsigned long long r; asm("mov.b64 %0,{%1,%2};" : "=l"(r) : "f"(a), "f"(b)); return r;
}
__device__ __forceinline__ float2 upk(unsigned long long v) {
    float2 r; asm("mov.b64 {%0,%1},%2;" : "=f"(r.x), "=f"(r.y) : "l"(v)); return r;
}
// q holds (xi, yi); nj holds (-xj, -yj). Returns squared dist (no EPS); s = packed diff.
__device__ __forceinline__ float dist2s(unsigned long long q, unsigned long long nj,
                                        unsigned long long& s) {
    asm("add.rn.f32x2 %0,%1,%2;" : "=l"(s) : "l"(q), "l"(nj));
    float2 f = upk(s);
    return fmaf(f.x, f.x, f.y * f.y);
}
__device__ __forceinline__ float dist2q(unsigned long long q, unsigned long long nj) {
    unsigned long long s; return dist2s(q, nj, s);
}

// ---------------- branch-free sorted inserts (FMNMX chains) ----------------
#define INS3(a0,a1,a2,d) do{ \
    float _t1 = fmaxf(a0,(d)), _t2 = fmaxf(a1,(d)); \
    a0 = fminf(a0,(d)); a1 = fminf(a1,_t1); a2 = fminf(a2,_t2); }while(0)

#define INS5(a0,a1,a2,a3,a4,d) do{ \
    float _t1 = fmaxf(a0,(d)), _t2 = fmaxf(a1,(d)), _t3 = fmaxf(a2,(d)), _t4 = fmaxf(a3,(d)); \
    a0 = fminf(a0,(d)); a1 = fminf(a1,_t1); a2 = fminf(a2,_t2); \
    a3 = fminf(a3,_t3); a4 = fminf(a4,_t4); }while(0)

// ---------------- warp k-min extraction ----------------
__device__ __forceinline__ float pop3(float& a0, float& a1, float& a2, int lane) {
    float bv = a0; int bl = lane;
#pragma unroll
    for (int off = 16; off; off >>= 1) {
        float ov = __shfl_down_sync(0xffffffffu, bv, off);
        int   ol = __shfl_down_sync(0xffffffffu, bl, off);
        if (ov < bv) { bv = ov; bl = ol; }
    }
    bv = __shfl_sync(0xffffffffu, bv, 0);
    bl = __shfl_sync(0xffffffffu, bl, 0);
    if (lane == bl) { a0 = a1; a1 = a2; a2 = INF; }
    return bv;
}
__device__ __forceinline__ float pop5(float& a0, float& a1, float& a2, float& a3, float& a4,
                                      int lane) {
    float bv = a0; int bl = lane;
#pragma unroll
    for (int off = 16; off; off >>= 1) {
        float ov = __shfl_down_sync(0xffffffffu, bv, off);
        int   ol = __shfl_down_sync(0xffffffffu, bl, off);
        if (ov < bv) { bv = ov; bl = ol; }
    }
    bv = __shfl_sync(0xffffffffu, bv, 0);
    bl = __shfl_sync(0xffffffffu, bl, 0);
    if (lane == bl) { a0 = a1; a1 = a2; a2 = a3; a3 = a4; a4 = INF; }
    return bv;
}

// ---------------- hex contribution (shared by loop + self-subtraction) ----------------
__device__ __forceinline__ void hex_contrib(float dx, float dy, float d2,
                                            float kth, float inv_sigma,
                                            float& wsum, float& wre, float& wim) {
    float dist = sqrtf(d2 + EPSF);
    float arg = (kth - dist) * inv_sigma;              // gate guarantees arg in (-18, ~10)
    float e = __expf(-arg);
    float w = __fdividef(1.0f, 1.0f + e);
    float c = dx;
    if (fabsf(c) < EPSF) c = c + EPSF;
    float n2 = fmaf(c, c, dy * dy);
    float inv = __fdividef(1.0f, n2);
    float un = (c * c - dy * dy) * inv;                // cos 2t
    float vn = (2.0f * c * dy) * inv;                  // sin 2t
    float re4 = un * un - vn * vn;                     // cos 4t
    float im4 = 2.0f * un * vn;                        // sin 4t
    wsum += w;
    wre = fmaf(w, re4, wre);
    wim = fmaf(w, im4, wim);
}

// ================ fused pairs kernel ================
// blocks [0,128): real kNN (8 pts/warp); [128,384): fake hex (4 pts/warp);
// [384,512): feasibility (8 rows/warp)
__global__ void __launch_bounds__(256) pairs_kernel(const float* __restrict__ real_in,
                                                    const float* __restrict__ fake_in) {
    __shared__ unsigned long long sneg[NP];
    __shared__ float rr[NP];
    __shared__ float s_acc[8];
    int bx = blockIdx.x;
    int warp = threadIdx.x >> 5, lane = threadIdx.x & 31;

    if (bx < 128) {
        // -------- real kNN: top-3 incl self, 8 pts/warp --------
        int b = bx >> 5;
        int ibase = (bx & 31) * 64;
        const float* base = real_in + b * NP * 3;
        for (int j = threadIdx.x; j < NP; j += 256)
            sneg[j] = pk(-base[j * 3], -base[j * 3 + 1]);
        __syncthreads();
        unsigned long long q[8];
        float acc[8][3];
#pragma unroll
        for (int p = 0; p < 8; p++) {
            float2 pp = upk(sneg[ibase + warp * 8 + p]);
            q[p] = pk(-pp.x, -pp.y);
            acc[p][0] = INF; acc[p][1] = INF; acc[p][2] = INF;
        }
#pragma unroll 2
        for (int j = lane; j < NP; j += 32) {
            unsigned long long nj = sneg[j];
#pragma unroll
            for (int p = 0; p < 8; p++) {
                float d = dist2q(q[p], nj);
                INS3(acc[p][0], acc[p][1], acc[p][2], d);
            }
        }
#pragma unroll
        for (int p = 0; p < 8; p++) {
            float o0 = pop3(acc[p][0], acc[p][1], acc[p][2], lane);
            float o1 = pop3(acc[p][0], acc[p][1], acc[p][2], lane);
            float o2 = pop3(acc[p][0], acc[p][1], acc[p][2], lane);
            if (lane == 0) {
                float* dst = &g_knn[0][b][(ibase + warp * 8 + p) * 3];
                dst[0] = sqrtf(o0 + EPSF); dst[1] = sqrtf(o1 + EPSF); dst[2] = sqrtf(o2 + EPSF);
            }
        }
    } else if (bx < 384) {
        // -------- fake: fused kNN + hexatic order, 4 pts/warp --------
        int bx2 = bx - 128;
        int b = bx2 >> 6;
        int ibase = (bx2 & 63) * 32;
        const float* base = fake_in + b * NP * 3;
        for (int j = threadIdx.x; j < NP; j += 256)
            sneg[j] = pk(-base[j * 3], -base[j * 3 + 1]);
        __syncthreads();
        unsigned long long q[4];
        float acc[4][5];
#pragma unroll
        for (int p = 0; p < 4; p++) {
            float2 pp = upk(sneg[ibase + warp * 4 + p]);
            q[p] = pk(-pp.x, -pp.y);
            acc[p][0] = INF; acc[p][1] = INF; acc[p][2] = INF; acc[p][3] = INF; acc[p][4] = INF;
        }
        // pass 1: top-5 including self (self contributes exact 0)
#pragma unroll 2
        for (int j = lane; j < NP; j += 32) {
            unsigned long long nj = sneg[j];
#pragma unroll
            for (int p = 0; p < 4; p++) {
                float d = dist2q(q[p], nj);
                INS5(acc[p][0], acc[p][1], acc[p][2], acc[p][3], acc[p][4], d);
            }
        }
        float kth[4], isg[4], lim2[4];
#pragma unroll
        for (int p = 0; p < 4; p++) {
            float o0 = pop5(acc[p][0], acc[p][1], acc[p][2], acc[p][3], acc[p][4], lane);
            float o1 = pop5(acc[p][0], acc[p][1], acc[p][2], acc[p][3], acc[p][4], lane);
            float o2 = pop5(acc[p][0], acc[p][1], acc[p][2], acc[p][3], acc[p][4], lane);
            float o3 = pop5(acc[p][0], acc[p][1], acc[p][2], acc[p][3], acc[p][4], lane); (void)o3;
            float o4 = pop5(acc[p][0], acc[p][1], acc[p][2], acc[p][3], acc[p][4], lane);
            if (lane == 0) {
                float* dst = &g_knn[1][b][(ibase + warp * 4 + p) * 3];
                dst[0] = sqrtf(o0 + EPSF); dst[1] = sqrtf(o1 + EPSF); dst[2] = sqrtf(o2 + EPSF);
            }
            float kv = sqrtf(o4 + EPSF);
            float sg = fmaxf(0.1f * fmaxf(kv, EPSF), EPSF);
            kth[p] = kv;
            isg[p] = __fdividef(1.0f, sg);
            float lim = kv + 18.0f * sg;   // beyond: w <= sigmoid(-18) ~ 1.5e-8
            lim2[p] = fmaf(lim, lim, -EPSF);
        }
        // pass 2
        float ws[4] = {0.f, 0.f, 0.f, 0.f};
        float wr[4] = {0.f, 0.f, 0.f, 0.f};
        float wi[4] = {0.f, 0.f, 0.f, 0.f};
#pragma unroll 2
        for (int j = lane; j < NP; j += 32) {
            unsigned long long nj = sneg[j];
#pragma unroll
            for (int p = 0; p < 4; p++) {
                unsigned long long s;
                float d2 = dist2s(q[p], nj, s);
                if (d2 <= lim2[p]) {
                    float2 dv = upk(s);
                    hex_contrib(dv.x, dv.y, d2, kth[p], isg[p], ws[p], wr[p], wi[p]);
                }
            }
        }
#pragma unroll
        for (int p = 0; p < 4; p++) {
#pragma unroll
            for (int off = 16; off; off >>= 1) {
                ws[p] += __shfl_down_sync(0xffffffffu, ws[p], off);
                wr[p] += __shfl_down_sync(0xffffffffu, wr[p], off);
                wi[p] += __shfl_down_sync(0xffffffffu, wi[p], off);
            }
        }
        if (lane == 0) {
            float psum = 0.0f;
#pragma unroll
            for (int p = 0; p < 4; p++) {
                float ss = 0.0f, sr = 0.0f, si = 0.0f;   // subtract self exactly once
                hex_contrib(0.0f, 0.0f, 0.0f, kth[p], isg[p], ss, sr, si);
                float wsum = ws[p] - ss, wre = wr[p] - sr, wim = wi[p] - si;
                psum += sqrtf(wre * wre + wim * wim) / fmaxf(wsum, EPSF);
            }
            s_acc[warp] = psum;
        }
        __syncthreads();
        if (threadIdx.x == 0) {
            float s = 0.0f;
            for (int w = 0; w < 8; w++) s += s_acc[w];
            g_hex_partial[bx2] = s;
        }
    } else {
        // -------- feasibility: warp-parallel lower triangle, 8 rows/warp --------
        int bx2 = bx - 384;
        int b = bx2 >> 5;
        int ibase = (bx2 & 31) * 64;
        const float* base = fake_in + b * NP * 3;
        for (int j = threadIdx.x; j < NP; j += 256) {
            sneg[j] = pk(-base[j * 3], -base[j * 3 + 1]);
            rr[j] = fabsf(base[j * 3 + 2]);
        }
        __syncthreads();
        unsigned long long q[8];
        float ri[8];
        int i0 = ibase + warp * 8;
#pragma unroll
        for (int p = 0; p < 8; p++) {
            float2 pp = upk(sneg[i0 + p]);
            q[p] = pk(-pp.x, -pp.y);
            ri[p] = rr[i0 + p];
        }
        float acc = 0.0f;
        int imax = i0 + 7;
        for (int j = lane; j < imax; j += 32) {
            unsigned long long nj = sneg[j];
            float rj = rr[j];
#pragma unroll
            for (int p = 0; p < 8; p++) {
                if (j < i0 + p) {                      // strict lower triangle
                    float sq = dist2q(q[p], nj);
                    float thr = ri[p] + rj - 1e-4f;
                    if (sq > 0.0f && thr > 0.0f && sq < thr * thr)
                        acc += thr - sqrtf(sq);
                }
            }
        }
#pragma unroll
        for (int off = 16; off; off >>= 1)
            acc += __shfl_down_sync(0xffffffffu, acc, off);
        if (lane == 0) s_acc[warp] = acc;
        __syncthreads();
        if (threadIdx.x == 0) {
            float s = 0.0f;
            for (int w = 0; w < 8; w++) s += s_acc[w];
            g_feas_partial[bx2] = s;
        }
    }
}

// ---------------- radix select: one block per (array, rank), 1024 thr ----------------
#define XY10 409,410,2047,2048,4095,4096,6143,6144,7781,7782
#define Z14  409,410,819,820,2047,2048,4095,4096,6143,6144,7371,7372,7781,7782
#define K6   307,308,3071,3072,5835,5836
#define R10(x) x,x,x,x,x,x,x,x,x,x
#define R14(x) x,x,x,x,x,x,x,x,x,x,x,x,x,x
#define R6(x)  x,x,x,x,x,x
#define S10 0,1,2,3,4,5,6,7,8,9
#define S14 0,1,2,3,4,5,6,7,8,9,10,11,12,13
#define S6  0,1,2,3,4,5

__constant__ unsigned short c_arr[116] = {
    R10(0), R10(1), R14(2), R10(3), R10(4), R14(5),
    R6(6), R6(7), R6(8), R6(9), R6(10), R6(11), R6(12), R6(13) };
__constant__ unsigned short c_rank[116] = {
    XY10, XY10, Z14, XY10, XY10, Z14, K6, K6, K6, K6, K6, K6, K6, K6 };
__constant__ unsigned char c_slot[116] = {
    S10, S10, S14, S10, S10, S14, S6, S6, S6, S6, S6, S6, S6, S6 };

__device__ __forceinline__ unsigned fkey(float f) {
    unsigned u = __float_as_uint(f);
    return (u & 0x80000000u) ? ~u : (u | 0x80000000u);
}

__global__ void __launch_bounds__(1024) select_kernel(const float* __restrict__ real_in,
                                                      const float* __restrict__ fake_in) {
    __shared__ unsigned skeys[8192];
    __shared__ int hist[2048];
    __shared__ int wtot[32], woff[32];
    __shared__ unsigned s_bin;
    __shared__ int s_rank;
    int task = blockIdx.x;
    int a = c_arr[task];
    int r = c_rank[task];
    int tid = threadIdx.x, lane = tid & 31, wid = tid >> 5;

    // load + transform keys into smem once (pad knn arrays to 8192 with max key)
    if (a < 6) {
        const float* src = (a < 3 ? real_in : fake_in) + (a % 3);
#pragma unroll
        for (int it = 0; it < 8; it++) {
            int idx = tid + it * 1024;
            skeys[idx] = fkey(src[idx * 3]);
        }
    } else {
        const float* src = &g_knn[0][0][0] + (a - 6) * (NP * 3);
#pragma unroll
        for (int it = 0; it < 8; it++) {
            int idx = tid + it * 1024;
            skeys[idx] = (idx < NP * 3) ? fkey(src[idx]) : 0xFFFFFFFFu;
        }
    }
    __syncthreads();

    unsigned prefix = 0;
#pragma unroll
    for (int level = 0; level < 3; level++) {
        int nb = (level < 2) ? 2048 : 1024;
        int shift = (level == 0) ? 21 : (level == 1 ? 10 : 0);
        for (int bI = tid; bI < nb; bI += 1024) hist[bI] = 0;
        __syncthreads();
#pragma unroll
        for (int it = 0; it < 8; it++) {
            unsigned k = skeys[tid + it * 1024];
            bool ok = (level == 0) ||
                      (level == 1 ? ((k >> 21) == prefix) : ((k >> 10) == prefix));
            unsigned act = __ballot_sync(0xffffffffu, ok);
            if (ok) {
                unsigned bin = (k >> shift) & (nb - 1);
                unsigned grp = __match_any_sync(act, bin);
                int ldr = __ffs(grp) - 1;
                if (lane == ldr) atomicAdd(&hist[bin], __popc(grp));
            }
        }
        __syncthreads();
        int per = nb >> 10;                 // 2 or 1 bins per thread
        int base = tid * per;
        int local = 0;
        for (int bI = 0; bI < per; bI++) local += hist[base + bI];
        int incl = local;
#pragma unroll
        for (int off = 1; off < 32; off <<= 1) {
            int v = __shfl_up_sync(0xffffffffu, incl, off);
            if (lane >= off) incl += v;
        }
        if (lane == 31) wtot[wid] = incl;
        __syncthreads();
        if (tid < 32) {
            int v = wtot[tid];
            int inc2 = v;
#pragma unroll
            for (int off = 1; off < 32; off <<= 1) {
                int u = __shfl_up_sync(0xffffffffu, inc2, off);
                if (tid >= off) inc2 += u;
            }
            woff[tid] = inc2 - v;
        }
        __syncthreads();
        int myExcl = woff[wid] + incl - local;
        if (r >= myExcl && r < myExcl + local) {
            int rr2 = r - myExcl;
            for (int bI = 0; bI < per; bI++) {
                int h = hist[base + bI];
                if (rr2 < h) { s_bin = base + bI; s_rank = rr2; break; }
                rr2 -= h;
            }
        }
        __syncthreads();
        prefix = (prefix << ((level == 2) ? 10 : 11)) | s_bin;
        r = s_rank;
        __syncthreads();
    }
    if (tid == 0) {
        unsigned key = prefix;
        unsigned u = (key & 0x80000000u) ? (key ^ 0x80000000u) : ~key;
        g_sel[a][c_slot[task]] = __uint_as_float(u);
    }
}

// ---------------- finalize ----------------
__device__ __forceinline__ float quant_sel(int a, int k, double q, int n) {
    double pos = q * (double)(n - 1);
    int lo = (int)pos;
    float fr = (float)(pos - (double)lo);
    float vlo = g_sel[a][2 * k], vhi = g_sel[a][2 * k + 1];
    return vlo + fr * (vhi - vlo);
}

__global__ void final_kernel(const float* __restrict__ fake_in,
                             const float* __restrict__ fo,
                             float* __restrict__ out) {
    __shared__ float red[256];
    __shared__ float s_sumr, s_hex, s_feas;
    int t = threadIdx.x;

    float s = 0.0f;
    for (int i = t; i < BSZ * NP; i += 256) s += fabsf(fake_in[i * 3 + 2]);
    red[t] = s; __syncthreads();
    for (int off = 128; off; off >>= 1) { if (t < off) red[t] += red[t + off]; __syncthreads(); }
    if (t == 0) s_sumr = red[0];
    __syncthreads();

    red[t] = g_hex_partial[t]; __syncthreads();
    for (int off = 128; off; off >>= 1) { if (t < off) red[t] += red[t + off]; __syncthreads(); }
    if (t == 0) s_hex = red[0];
    __syncthreads();

    red[t] = (t < 128) ? g_feas_partial[t] : 0.0f; __syncthreads();
    for (int off = 128; off; off >>= 1) { if (t < off) red[t] += red[t + off]; __syncthreads(); }
    if (t == 0) s_feas = red[0];
    __syncthreads();

    if (t == 0) {
        const double q7[7] = {0.05, 0.1, 0.25, 0.5, 0.75, 0.9, 0.95};
        const double q5[5] = {0.05, 0.25, 0.5, 0.75, 0.95};
        const double q3[3] = {0.05, 0.5, 0.95};
        float loss = 0.0f;
        {   // radius loss (z): arrays real=2, fake=5
            float acc = 0.0f;
            for (int k = 0; k < 7; k++) {
                float d = quant_sel(5, k, q7[k], 8192) - quant_sel(2, k, q7[k], 8192);
                acc += d * d;
            }
            loss += acc / 7.0f;
        }
        {   // grid density loss (x: 0/3, y: 1/4)
            float ax = 0.0f, ay = 0.0f;
            for (int k = 0; k < 5; k++) {
                float dx = quant_sel(3, k, q5[k], 8192) - quant_sel(0, k, q5[k], 8192);
                float dy = quant_sel(4, k, q5[k], 8192) - quant_sel(1, k, q5[k], 8192);
                ax += dx * dx; ay += dy * dy;
            }
            loss += 0.5f * (ax / 5.0f + ay / 5.0f);
        }
        {   // distance loss: per-batch kNN quantiles (real 6+b, fake 10+b)
            float acc = 0.0f;
            for (int b = 0; b < BSZ; b++)
                for (int k = 0; k < 3; k++) {
                    float d = quant_sel(10 + b, k, q3[k], NP * 3) -
                              quant_sel(6 + b,  k, q3[k], NP * 3);
                    acc += d * d;
                }
            loss += acc / 12.0f;
        }
        loss += -s_hex / (float)(BSZ * NP);                 // grid order
        loss += s_feas / ((float)NP * s_sumr);              // feasibility
        {   // gan loss
            float g = 0.0f;
            for (int i = 0; i < BSZ; i++) {
                float p = fo[i];
                g += 0.9f * fmaxf(logf(p), -100.0f) + 0.1f * fmaxf(logf(1.0f - p), -100.0f);
            }
            loss += -g / (float)BSZ;
        }
        out[0] = loss;
    }
}

// ---------------- launch ----------------
extern "C" void kernel_launch(void* const* d_in, const int* in_sizes, int n_in,
                              void* d_out, int out_size) {
    const float* real_in = (const float*)d_in[0];
    const float* fake_in = (const float*)d_in[1];
    const float* fo      = (const float*)d_in[2];
    float* out = (float*)d_out;

    pairs_kernel <<<512, 256>>>(real_in, fake_in);
    select_kernel<<<116, 1024>>>(real_in, fake_in);
    final_kernel <<<1,   256>>>(fake_in, fo, out);
}

// round 6
// speedup vs baseline: 1.1801x; 1.1801x over previous
#include <cuda_runtime.h>
#include <math_constants.h>
#include <math.h>

#define BSZ 4
#define NP  2048
#define EPSF 1e-6f
#define INF  CUDART_INF_F

// ---------------- scratch ----------------
__device__ float g_knn[2][BSZ][NP * 3];   // sqrt'd 3NN (incl self): real=0, fake=1
__device__ float g_sel[14][14];           // selected order statistics
__device__ float g_hex_partial[256];
__device__ float g_feas_partial[256];

// ---------------- packed f32x2 helpers ----------------
__device__ __forceinline__ unsigned long long pk(float a, float b) {
    unsigned long long r; asm("mov.b64 %0,{%1,%2};" : "=l"(r) : "f"(a), "f"(b)); return r;
}
__device__ __forceinline__ float2 upk(unsigned long long v) {
    float2 r; asm("mov.b64 {%0,%1},%2;" : "=f"(r.x), "=f"(r.y) : "l"(v)); return r;
}
// q holds (xi, yi); nj holds (-xj, -yj). Returns squared dist (no EPS); s = packed diff.
__device__ __forceinline__ float dist2s(unsigned long long q, unsigned long long nj,
                                        unsigned long long& s) {
    asm("add.rn.f32x2 %0,%1,%2;" : "=l"(s) : "l"(q), "l"(nj));
    float2 f = upk(s);
    return fmaf(f.x, f.x, f.y * f.y);
}
__device__ __forceinline__ float dist2q(unsigned long long q, unsigned long long nj) {
    unsigned long long s; return dist2s(q, nj, s);
}

// ---------------- branch-free sorted inserts (FMNMX networks, no divergence) -------
// invariant a0<=a1<=a2 maintained; exact top-k update
#define INS3(a0,a1,a2,d) do{ \
    float _m1 = fmaxf(a0,(d)), _m2 = fmaxf(a1,(d)); \
    a0 = fminf(a0,(d)); a1 = fminf(a1,_m1); a2 = fminf(a2,_m2); }while(0)

#define INS5(a0,a1,a2,a3,a4,d) do{ \
    float _m1 = fmaxf(a0,(d)), _m2 = fmaxf(a1,(d)), _m3 = fmaxf(a2,(d)), _m4 = fmaxf(a3,(d)); \
    a0 = fminf(a0,(d)); a1 = fminf(a1,_m1); a2 = fminf(a2,_m2); \
    a3 = fminf(a3,_m3); a4 = fminf(a4,_m4); }while(0)

// ---------------- warp k-min extraction ----------------
__device__ __forceinline__ float pop3(float& a0, float& a1, float& a2, int lane) {
    float bv = a0; int bl = lane;
#pragma unroll
    for (int off = 16; off; off >>= 1) {
        float ov = __shfl_down_sync(0xffffffffu, bv, off);
        int   ol = __shfl_down_sync(0xffffffffu, bl, off);
        if (ov < bv) { bv = ov; bl = ol; }
    }
    bv = __shfl_sync(0xffffffffu, bv, 0);
    bl = __shfl_sync(0xffffffffu, bl, 0);
    if (lane == bl) { a0 = a1; a1 = a2; a2 = INF; }
    return bv;
}
__device__ __forceinline__ float pop5(float& a0, float& a1, float& a2, float& a3, float& a4,
                                      int lane) {
    float bv = a0; int bl = lane;
#pragma unroll
    for (int off = 16; off; off >>= 1) {
        float ov = __shfl_down_sync(0xffffffffu, bv, off);
        int   ol = __shfl_down_sync(0xffffffffu, bl, off);
        if (ov < bv) { bv = ov; bl = ol; }
    }
    bv = __shfl_sync(0xffffffffu, bv, 0);
    bl = __shfl_sync(0xffffffffu, bl, 0);
    if (lane == bl) { a0 = a1; a1 = a2; a2 = a3; a3 = a4; a4 = INF; }
    return bv;
}

// ---------------- hex contribution (shared by loop + self-subtraction) ----------------
__device__ __forceinline__ void hex_contrib(float dx, float dy, float d2,
                                            float kth, float inv_sigma,
                                            float& wsum, float& wre, float& wim) {
    float dist = sqrtf(d2 + EPSF);
    float arg = (kth - dist) * inv_sigma;              // gate guarantees arg in (-18, ~10)
    float e = __expf(-arg);
    float w = __fdividef(1.0f, 1.0f + e);
    float c = dx;
    if (fabsf(c) < EPSF) c = c + EPSF;
    float n2 = fmaf(c, c, dy * dy);
    float inv = __fdividef(1.0f, n2);
    float un = (c * c - dy * dy) * inv;                // cos 2t
    float vn = (2.0f * c * dy) * inv;                  // sin 2t
    float re4 = un * un - vn * vn;                     // cos 4t
    float im4 = 2.0f * un * vn;                        // sin 4t
    wsum += w;
    wre = fmaf(w, re4, wre);
    wim = fmaf(w, im4, wim);
}

// ================ fused pairs kernel: blocks [0,256) real-kNN, [256,512) fake hex,
// ================ [512,768) feasibility — all 4 pts/warp ================
__global__ void __launch_bounds__(256, 5) pairs_kernel(const float* __restrict__ real_in,
                                                       const float* __restrict__ fake_in) {
    __shared__ unsigned long long sneg[NP];
    __shared__ float rr[NP];
    __shared__ float s_acc[8];
    int bx = blockIdx.x;
    int warp = threadIdx.x >> 5, lane = threadIdx.x & 31;

    if (bx < 256) {
        // -------- real kNN: top-3 incl self, 4 pts/warp --------
        int b = bx >> 6;
        int ibase = (bx & 63) * 32;
        const float* base = real_in + b * NP * 3;
        for (int j = threadIdx.x; j < NP; j += 256)
            sneg[j] = pk(-base[j * 3], -base[j * 3 + 1]);
        __syncthreads();
        unsigned long long q[4];
        float acc[4][3];
#pragma unroll
        for (int p = 0; p < 4; p++) {
            float2 pp = upk(sneg[ibase + warp * 4 + p]);
            q[p] = pk(-pp.x, -pp.y);
            acc[p][0] = INF; acc[p][1] = INF; acc[p][2] = INF;
        }
#pragma unroll 2
        for (int j = lane; j < NP; j += 32) {
            unsigned long long nj = sneg[j];
#pragma unroll
            for (int p = 0; p < 4; p++) {
                float d = dist2q(q[p], nj);
                INS3(acc[p][0], acc[p][1], acc[p][2], d);
            }
        }
#pragma unroll
        for (int p = 0; p < 4; p++) {
            float o0 = pop3(acc[p][0], acc[p][1], acc[p][2], lane);
            float o1 = pop3(acc[p][0], acc[p][1], acc[p][2], lane);
            float o2 = pop3(acc[p][0], acc[p][1], acc[p][2], lane);
            if (lane == 0) {
                float* dst = &g_knn[0][b][(ibase + warp * 4 + p) * 3];
                dst[0] = sqrtf(o0 + EPSF); dst[1] = sqrtf(o1 + EPSF); dst[2] = sqrtf(o2 + EPSF);
            }
        }
    } else if (bx < 512) {
        // -------- fake: fused kNN + hexatic order, 4 pts/warp --------
        int bx2 = bx - 256;
        int b = bx2 >> 6;
        int ibase = (bx2 & 63) * 32;
        const float* base = fake_in + b * NP * 3;
        for (int j = threadIdx.x; j < NP; j += 256)
            sneg[j] = pk(-base[j * 3], -base[j * 3 + 1]);
        __syncthreads();
        unsigned long long q[4];
        float acc[4][5];
#pragma unroll
        for (int p = 0; p < 4; p++) {
            float2 pp = upk(sneg[ibase + warp * 4 + p]);
            q[p] = pk(-pp.x, -pp.y);
            acc[p][0] = INF; acc[p][1] = INF; acc[p][2] = INF; acc[p][3] = INF; acc[p][4] = INF;
        }
        // pass 1: top-5 including self (self contributes exact 0)
#pragma unroll 2
        for (int j = lane; j < NP; j += 32) {
            unsigned long long nj = sneg[j];
#pragma unroll
            for (int p = 0; p < 4; p++) {
                float d = dist2q(q[p], nj);
                INS5(acc[p][0], acc[p][1], acc[p][2], acc[p][3], acc[p][4], d);
            }
        }
        float kth[4], isg[4], lim2[4];
#pragma unroll
        for (int p = 0; p < 4; p++) {
            float o0 = pop5(acc[p][0], acc[p][1], acc[p][2], acc[p][3], acc[p][4], lane);
            float o1 = pop5(acc[p][0], acc[p][1], acc[p][2], acc[p][3], acc[p][4], lane);
            float o2 = pop5(acc[p][0], acc[p][1], acc[p][2], acc[p][3], acc[p][4], lane);
            float o3 = pop5(acc[p][0], acc[p][1], acc[p][2], acc[p][3], acc[p][4], lane); (void)o3;
            float o4 = pop5(acc[p][0], acc[p][1], acc[p][2], acc[p][3], acc[p][4], lane);
            if (lane == 0) {
                float* dst = &g_knn[1][b][(ibase + warp * 4 + p) * 3];
                dst[0] = sqrtf(o0 + EPSF); dst[1] = sqrtf(o1 + EPSF); dst[2] = sqrtf(o2 + EPSF);
            }
            float kv = sqrtf(o4 + EPSF);
            float sg = fmaxf(0.1f * fmaxf(kv, EPSF), EPSF);
            kth[p] = kv;
            isg[p] = __fdividef(1.0f, sg);
            float lim = kv + 18.0f * sg;   // beyond: w <= sigmoid(-18) ~ 1.5e-8
            lim2[p] = fmaf(lim, lim, -EPSF);
        }
        // pass 2 (gate rarely true per-lane; keep branch)
        float ws[4] = {0.f, 0.f, 0.f, 0.f};
        float wr[4] = {0.f, 0.f, 0.f, 0.f};
        float wi[4] = {0.f, 0.f, 0.f, 0.f};
#pragma unroll 2
        for (int j = lane; j < NP; j += 32) {
            unsigned long long nj = sneg[j];
#pragma unroll
            for (int p = 0; p < 4; p++) {
                unsigned long long s;
                float d2 = dist2s(q[p], nj, s);
                if (d2 <= lim2[p]) {
                    float2 dv = upk(s);
                    hex_contrib(dv.x, dv.y, d2, kth[p], isg[p], ws[p], wr[p], wi[p]);
                }
            }
        }
#pragma unroll
        for (int p = 0; p < 4; p++) {
#pragma unroll
            for (int off = 16; off; off >>= 1) {
                ws[p] += __shfl_down_sync(0xffffffffu, ws[p], off);
                wr[p] += __shfl_down_sync(0xffffffffu, wr[p], off);
                wi[p] += __shfl_down_sync(0xffffffffu, wi[p], off);
            }
        }
        if (lane == 0) {
            float psum = 0.0f;
#pragma unroll
            for (int p = 0; p < 4; p++) {
                float ss = 0.0f, sr = 0.0f, si = 0.0f;   // subtract self exactly once
                hex_contrib(0.0f, 0.0f, 0.0f, kth[p], isg[p], ss, sr, si);
                float wsum = ws[p] - ss, wre = wr[p] - sr, wim = wi[p] - si;
                psum += sqrtf(wre * wre + wim * wim) / fmaxf(wsum, EPSF);
            }
            s_acc[warp] = psum;
        }
        __syncthreads();
        if (threadIdx.x == 0) {
            float s = 0.0f;
            for (int w = 0; w < 8; w++) s += s_acc[w];
            g_hex_partial[bx2] = s;
        }
    } else {
        // -------- feasibility: warp-parallel lower triangle, 4 rows/warp --------
        int bx2 = bx - 512;
        int b = bx2 >> 6;
        int ibase = (bx2 & 63) * 32;
        const float* base = fake_in + b * NP * 3;
        for (int j = threadIdx.x; j < NP; j += 256) {
            sneg[j] = pk(-base[j * 3], -base[j * 3 + 1]);
            rr[j] = fabsf(base[j * 3 + 2]);
        }
        __syncthreads();
        unsigned long long q[4];
        float ri[4];
        int i0 = ibase + warp * 4;
#pragma unroll
        for (int p = 0; p < 4; p++) {
            float2 pp = upk(sneg[i0 + p]);
            q[p] = pk(-pp.x, -pp.y);
            ri[p] = rr[i0 + p];
        }
        float acc = 0.0f;
        int imax = i0 + 3;
        for (int j = lane; j < imax; j += 32) {
            unsigned long long nj = sneg[j];
            float rj = rr[j];
#pragma unroll
            for (int p = 0; p < 4; p++) {
                if (j < i0 + p) {                      // strict lower triangle
                    float sq = dist2q(q[p], nj);
                    float thr = ri[p] + rj - 1e-4f;
                    if (sq > 0.0f && thr > 0.0f && sq < thr * thr)
                        acc += thr - sqrtf(sq);
                }
            }
        }
#pragma unroll
        for (int off = 16; off; off >>= 1)
            acc += __shfl_down_sync(0xffffffffu, acc, off);
        if (lane == 0) s_acc[warp] = acc;
        __syncthreads();
        if (threadIdx.x == 0) {
            float s = 0.0f;
            for (int w = 0; w < 8; w++) s += s_acc[w];
            g_feas_partial[bx2] = s;
        }
    }
}

// ---------------- radix select: one block per (array, rank), 1024 thr ----------------
#define XY10 409,410,2047,2048,4095,4096,6143,6144,7781,7782
#define Z14  409,410,819,820,2047,2048,4095,4096,6143,6144,7371,7372,7781,7782
#define K6   307,308,3071,3072,5835,5836
#define R10(x) x,x,x,x,x,x,x,x,x,x
#define R14(x) x,x,x,x,x,x,x,x,x,x,x,x,x,x
#define R6(x)  x,x,x,x,x,x
#define S10 0,1,2,3,4,5,6,7,8,9
#define S14 0,1,2,3,4,5,6,7,8,9,10,11,12,13
#define S6  0,1,2,3,4,5

__constant__ unsigned short c_arr[116] = {
    R10(0), R10(1), R14(2), R10(3), R10(4), R14(5),
    R6(6), R6(7), R6(8), R6(9), R6(10), R6(11), R6(12), R6(13) };
__constant__ unsigned short c_rank[116] = {
    XY10, XY10, Z14, XY10, XY10, Z14, K6, K6, K6, K6, K6, K6, K6, K6 };
__constant__ unsigned char c_slot[116] = {
    S10, S10, S14, S10, S10, S14, S6, S6, S6, S6, S6, S6, S6, S6 };

__device__ __forceinline__ unsigned fkey(float f) {
    unsigned u = __float_as_uint(f);
    return (u & 0x80000000u) ? ~u : (u | 0x80000000u);
}

__global__ void __launch_bounds__(1024) select_kernel(const float* __restrict__ real_in,
                                                      const float* __restrict__ fake_in) {
    __shared__ unsigned skeys[8192];
    __shared__ int hist[2048];
    __shared__ int wtot[32], woff[32];
    __shared__ unsigned s_bin;
    __shared__ int s_rank;
    int task = blockIdx.x;
    int a = c_arr[task];
    int r = c_rank[task];
    int tid = threadIdx.x, lane = tid & 31, wid = tid >> 5;

    // load + transform keys into smem once (pad knn arrays to 8192 with max key)
    if (a < 6) {
        const float* src = (a < 3 ? real_in : fake_in) + (a % 3);
#pragma unroll
        for (int it = 0; it < 8; it++) {
            int idx = tid + it * 1024;
            skeys[idx] = fkey(src[idx * 3]);
        }
    } else {
        const float* src = &g_knn[0][0][0] + (a - 6) * (NP * 3);
#pragma unroll
        for (int it = 0; it < 8; it++) {
            int idx = tid + it * 1024;
            skeys[idx] = (idx < NP * 3) ? fkey(src[idx]) : 0xFFFFFFFFu;
        }
    }
    __syncthreads();

    unsigned prefix = 0;
#pragma unroll
    for (int level = 0; level < 3; level++) {
        int nb = (level < 2) ? 2048 : 1024;
        int shift = (level == 0) ? 21 : (level == 1 ? 10 : 0);
        for (int bI = tid; bI < nb; bI += 1024) hist[bI] = 0;
        __syncthreads();
#pragma unroll
        for (int it = 0; it < 8; it++) {
            unsigned k = skeys[tid + it * 1024];
            bool ok = (level == 0) ||
                      (level == 1 ? ((k >> 21) == prefix) : ((k >> 10) == prefix));
            unsigned act = __ballot_sync(0xffffffffu, ok);
            if (ok) {
                unsigned bin = (k >> shift) & (nb - 1);
                unsigned grp = __match_any_sync(act, bin);
                int ldr = __ffs(grp) - 1;
                if (lane == ldr) atomicAdd(&hist[bin], __popc(grp));
            }
        }
        __syncthreads();
        int per = nb >> 10;                 // 2 or 1 bins per thread
        int base = tid * per;
        int local = 0;
        for (int bI = 0; bI < per; bI++) local += hist[base + bI];
        int incl = local;
#pragma unroll
        for (int off = 1; off < 32; off <<= 1) {
            int v = __shfl_up_sync(0xffffffffu, incl, off);
            if (lane >= off) incl += v;
        }
        if (lane == 31) wtot[wid] = incl;
        __syncthreads();
        if (tid < 32) {
            int v = wtot[tid];
            int inc2 = v;
#pragma unroll
            for (int off = 1; off < 32; off <<= 1) {
                int u = __shfl_up_sync(0xffffffffu, inc2, off);
                if (tid >= off) inc2 += u;
            }
            woff[tid] = inc2 - v;
        }
        __syncthreads();
        int myExcl = woff[wid] + incl - local;
        if (r >= myExcl && r < myExcl + local) {
            int rr2 = r - myExcl;
            for (int bI = 0; bI < per; bI++) {
                int h = hist[base + bI];
                if (rr2 < h) { s_bin = base + bI; s_rank = rr2; break; }
                rr2 -= h;
            }
        }
        __syncthreads();
        prefix = (prefix << ((level == 2) ? 10 : 11)) | s_bin;
        r = s_rank;
        __syncthreads();
    }
    if (tid == 0) {
        unsigned key = prefix;
        unsigned u = (key & 0x80000000u) ? (key ^ 0x80000000u) : ~key;
        g_sel[a][c_slot[task]] = __uint_as_float(u);
    }
}

// ---------------- finalize ----------------
__device__ __forceinline__ float quant_sel(int a, int k, double q, int n) {
    double pos = q * (double)(n - 1);
    int lo = (int)pos;
    float fr = (float)(pos - (double)lo);
    float vlo = g_sel[a][2 * k], vhi = g_sel[a][2 * k + 1];
    return vlo + fr * (vhi - vlo);
}

__global__ void final_kernel(const float* __restrict__ fake_in,
                             const float* __restrict__ fo,
                             float* __restrict__ out) {
    __shared__ float red[256];
    __shared__ float s_sumr, s_hex, s_feas;
    int t = threadIdx.x;

    float s = 0.0f;
    for (int i = t; i < BSZ * NP; i += 256) s += fabsf(fake_in[i * 3 + 2]);
    red[t] = s; __syncthreads();
    for (int off = 128; off; off >>= 1) { if (t < off) red[t] += red[t + off]; __syncthreads(); }
    if (t == 0) s_sumr = red[0];
    __syncthreads();

    red[t] = g_hex_partial[t]; __syncthreads();
    for (int off = 128; off; off >>= 1) { if (t < off) red[t] += red[t + off]; __syncthreads(); }
    if (t == 0) s_hex = red[0];
    __syncthreads();

    red[t] = g_feas_partial[t]; __syncthreads();
    for (int off = 128; off; off >>= 1) { if (t < off) red[t] += red[t + off]; __syncthreads(); }
    if (t == 0) s_feas = red[0];
    __syncthreads();

    if (t == 0) {
        const double q7[7] = {0.05, 0.1, 0.25, 0.5, 0.75, 0.9, 0.95};
        const double q5[5] = {0.05, 0.25, 0.5, 0.75, 0.95};
        const double q3[3] = {0.05, 0.5, 0.95};
        float loss = 0.0f;
        {   // radius loss (z): arrays real=2, fake=5
            float acc = 0.0f;
            for (int k = 0; k < 7; k++) {
                float d = quant_sel(5, k, q7[k], 8192) - quant_sel(2, k, q7[k], 8192);
                acc += d * d;
            }
            loss += acc / 7.0f;
        }
        {   // grid density loss (x: 0/3, y: 1/4)
            float ax = 0.0f, ay = 0.0f;
            for (int k = 0; k < 5; k++) {
                float dx = quant_sel(3, k, q5[k], 8192) - quant_sel(0, k, q5[k], 8192);
                float dy = quant_sel(4, k, q5[k], 8192) - quant_sel(1, k, q5[k], 8192);
                ax += dx * dx; ay += dy * dy;
            }
            loss += 0.5f * (ax / 5.0f + ay / 5.0f);
        }
        {   // distance loss: per-batch kNN quantiles (real 6+b, fake 10+b)
            float acc = 0.0f;
            for (int b = 0; b < BSZ; b++)
                for (int k = 0; k < 3; k++) {
                    float d = quant_sel(10 + b, k, q3[k], NP * 3) -
                              quant_sel(6 + b,  k, q3[k], NP * 3);
                    acc += d * d;
                }
            loss += acc / 12.0f;
        }
        loss += -s_hex / (float)(BSZ * NP);                 // grid order
        loss += s_feas / ((float)NP * s_sumr);              // feasibility
        {   // gan loss
            float g = 0.0f;
            for (int i = 0; i < BSZ; i++) {
                float p = fo[i];
                g += 0.9f * fmaxf(logf(p), -100.0f) + 0.1f * fmaxf(logf(1.0f - p), -100.0f);
            }
            loss += -g / (float)BSZ;
        }
        out[0] = loss;
    }
}

// ---------------- launch ----------------
extern "C" void kernel_launch(void* const* d_in, const int* in_sizes, int n_in,
                              void* d_out, int out_size) {
    const float* real_in = (const float*)d_in[0];
    const float* fake_in = (const float*)d_in[1];
    const float* fo      = (const float*)d_in[2];
    float* out = (float*)d_out;

    pairs_kernel <<<768, 256>>>(real_in, fake_in);
    select_kernel<<<116, 1024>>>(real_in, fake_in);
    final_kernel <<<1,   256>>>(fake_in, fo, out);
}